// round 1
// baseline (speedup 1.0000x reference)
#include <cuda_runtime.h>

#define NB 64
#define N 1024
#define ITERS 10

// Scratch potentials (allocation-free): u[b][i], v[b][j]
__device__ __align__(16) float g_u[NB * N];
__device__ __align__(16) float g_v[NB * N];

__device__ __forceinline__ float clampA(float m) {
    // clip(M, -25, 25) / 0.1
    return fminf(fmaxf(m, -25.0f), 25.0f) * 10.0f;
}

__global__ void init_v_kernel() {
    int t = blockIdx.x * blockDim.x + threadIdx.x;
    if (t < NB * N) g_v[t] = 0.0f;
}

// u[b][i] = LSE_j( A[b][i][j] - v[b][j] ), one warp per row.
__global__ void __launch_bounds__(256) row_lse_kernel(const float* __restrict__ M) {
    int warp = (blockIdx.x * 256 + threadIdx.x) >> 5;   // global row id, 0..65535
    int lane = threadIdx.x & 31;
    int b = warp >> 10;
    int i = warp & (N - 1);

    const float4* __restrict__ row4 = reinterpret_cast<const float4*>(M + ((size_t)b * N + i) * N);
    const float4* __restrict__ v4   = reinterpret_cast<const float4*>(g_v + b * N);

    float x[32];
    float mx = -1e30f;
#pragma unroll
    for (int k = 0; k < 8; k++) {
        int idx = lane + 32 * k;
        float4 a = row4[idx];
        float4 v = v4[idx];
        float x0 = clampA(a.x) - v.x;
        float x1 = clampA(a.y) - v.y;
        float x2 = clampA(a.z) - v.z;
        float x3 = clampA(a.w) - v.w;
        x[4 * k + 0] = x0; x[4 * k + 1] = x1;
        x[4 * k + 2] = x2; x[4 * k + 3] = x3;
        mx = fmaxf(mx, fmaxf(fmaxf(x0, x1), fmaxf(x2, x3)));
    }
#pragma unroll
    for (int o = 16; o > 0; o >>= 1)
        mx = fmaxf(mx, __shfl_xor_sync(0xFFFFFFFFu, mx, o));

    float s = 0.0f;
#pragma unroll
    for (int k = 0; k < 32; k++)
        s += __expf(x[k] - mx);
#pragma unroll
    for (int o = 16; o > 0; o >>= 1)
        s += __shfl_xor_sync(0xFFFFFFFFu, s, o);

    if (lane == 0)
        g_u[b * N + i] = mx + __logf(s);
}

// v[b][j] = LSE_i( A[b][i][j] - u[b][i] ), one thread per column.
// Block: 128 threads = 128 columns; grid (8 col-tiles, 64 batches).
__global__ void __launch_bounds__(128) col_lse_kernel(const float* __restrict__ M) {
    int b = blockIdx.y;
    int j = blockIdx.x * 128 + threadIdx.x;

    __shared__ float us[N];
    for (int k = threadIdx.x; k < N; k += 128)
        us[k] = g_u[b * N + k];
    __syncthreads();

    const float* __restrict__ base = M + (size_t)b * N * N + j;

    // Two interleaved online-LSE accumulators (rows [0,512) and [512,1024))
    float m0 = -1e30f, s0 = 0.0f;
    float m1 = -1e30f, s1 = 0.0f;

#pragma unroll 4
    for (int i = 0; i < N / 2; i++) {
        float a0 = base[(size_t)i * N];
        float a1 = base[(size_t)(i + N / 2) * N];
        float x0 = clampA(a0) - us[i];
        float x1 = clampA(a1) - us[i + N / 2];

        float nm0 = fmaxf(m0, x0);
        s0 = s0 * __expf(m0 - nm0) + __expf(x0 - nm0);
        m0 = nm0;

        float nm1 = fmaxf(m1, x1);
        s1 = s1 * __expf(m1 - nm1) + __expf(x1 - nm1);
        m1 = nm1;
    }

    float m = fmaxf(m0, m1);
    float s = s0 * __expf(m0 - m) + s1 * __expf(m1 - m);
    g_v[b * N + j] = m + __logf(s);
}

// out = exp(A - u_i - v_j), float4-vectorized.
__global__ void __launch_bounds__(256) finalize_kernel(const float* __restrict__ M,
                                                       float* __restrict__ out) {
    size_t t = (size_t)blockIdx.x * 256 + threadIdx.x;  // float4 index
    int j4 = (int)(t & 255);          // 256 float4 per row
    size_t r = t >> 8;                // global row id
    int b = (int)(r >> 10);

    float u = g_u[r];
    float4 v = reinterpret_cast<const float4*>(g_v + b * N)[j4];
    float4 a = reinterpret_cast<const float4*>(M)[t];

    float4 o;
    o.x = __expf(clampA(a.x) - u - v.x);
    o.y = __expf(clampA(a.y) - u - v.y);
    o.z = __expf(clampA(a.z) - u - v.z);
    o.w = __expf(clampA(a.w) - u - v.w);
    reinterpret_cast<float4*>(out)[t] = o;
}

extern "C" void kernel_launch(void* const* d_in, const int* in_sizes, int n_in,
                              void* d_out, int out_size) {
    const float* M = (const float*)d_in[0];
    float* out = (float*)d_out;

    init_v_kernel<<<(NB * N + 255) / 256, 256>>>();

    for (int it = 0; it < ITERS; it++) {
        // 64*1024 rows, 8 warps/block
        row_lse_kernel<<<(NB * N) / 8, 256>>>(M);
        col_lse_kernel<<<dim3(8, NB), 128>>>(M);
    }

    // 64*1024*1024/4 float4s, 256 threads/block
    finalize_kernel<<<(NB * N * (N / 4)) / 256, 256>>>(M, out);
}